// round 15
// baseline (speedup 1.0000x reference)
#include <cuda_runtime.h>
#include <cuda_fp16.h>
#include <cstdint>

#define BATCH 16
#define CIN   256
#define HWN   4096
#define DHEAD 32
#define NHEAD 8
#define MQ    256

// ---------------- scratch (device globals) -----------------------------------
__device__ float g_ctxT[BATCH * DHEAD * DHEAD];   // UNNORMALIZED ctxT'
__device__ float g_rs[BATCH * DHEAD];             // row exp-sums S_e
__device__ float g_Wkv[DHEAD * CIN]; __device__ float g_bkv[DHEAD];
__device__ float g_bq [MQ];          __device__ float g_bp [CIN];
__device__ __half g_WH[2][MQ * CIN];
__device__ __half g_XIN[(size_t)BATCH * CIN * HWN];

// ---------------- f32x2 helpers ------------------------------------------------
#define PACKF2(u, lo, hi) asm("mov.b64 %0, {%1, %2};" : "=l"(u) : "f"(lo), "f"(hi))
#define UNPACKF2(lo, hi, u) asm("mov.b64 {%0, %1}, %2;" : "=f"(lo), "=f"(hi) : "l"(u))
#define FMAF2(c, a, b) asm("fma.rn.f32x2 %0, %1, %2, %0;" : "+l"(c) : "l"(a), "l"(b))

// ---------------- mma / async helpers -------------------------------------------
__device__ __forceinline__ void ldsm4(uint32_t* r, uint32_t addr) {
    asm volatile("ldmatrix.sync.aligned.m8n8.x4.shared.b16 {%0,%1,%2,%3}, [%4];\n"
        : "=r"(r[0]), "=r"(r[1]), "=r"(r[2]), "=r"(r[3]) : "r"(addr));
}
__device__ __forceinline__ void ldsm4t(uint32_t* r, uint32_t addr) {
    asm volatile("ldmatrix.sync.aligned.m8n8.x4.trans.shared.b16 {%0,%1,%2,%3}, [%4];\n"
        : "=r"(r[0]), "=r"(r[1]), "=r"(r[2]), "=r"(r[3]) : "r"(addr));
}
__device__ __forceinline__ void mma_f16(float* c, const uint32_t* a,
                                        uint32_t b0, uint32_t b1) {
    asm volatile(
        "mma.sync.aligned.m16n8k16.row.col.f32.f16.f16.f32 "
        "{%0,%1,%2,%3}, {%4,%5,%6,%7}, {%8,%9}, {%0,%1,%2,%3};\n"
        : "+f"(c[0]), "+f"(c[1]), "+f"(c[2]), "+f"(c[3])
        : "r"(a[0]), "r"(a[1]), "r"(a[2]), "r"(a[3]), "r"(b0), "r"(b1));
}
__device__ __forceinline__ uint32_t packh2(__half a, __half b) {
    return (uint32_t)__half_as_ushort(a) | ((uint32_t)__half_as_ushort(b) << 16);
}
__device__ __forceinline__ void cp16(uint32_t saddr, const void* gptr) {
    asm volatile("cp.async.cg.shared.global [%0], [%1], 16;" :: "r"(saddr), "l"(gptr));
}
#define CP_COMMIT() asm volatile("cp.async.commit_group;" ::: "memory")
#define CP_WAIT0()  asm volatile("cp.async.wait_group 0;" ::: "memory")

// ---------------- 1) fold BN + fp16 weight plane + zero accumulators -----------
__global__ void fold_kernel(
    const float* __restrict__ Wq, const float* __restrict__ gq, const float* __restrict__ bq,
    const float* __restrict__ mq, const float* __restrict__ vq,
    const float* __restrict__ Wkv, const float* __restrict__ gkv, const float* __restrict__ bkv,
    const float* __restrict__ mkv, const float* __restrict__ vkv,
    const float* __restrict__ Wp, const float* __restrict__ gp, const float* __restrict__ bp,
    const float* __restrict__ mp, const float* __restrict__ vp)
{
    int t = blockIdx.x * blockDim.x + threadIdx.x;
    int stride = gridDim.x * blockDim.x;
    const float eps = 1e-5f;
    for (int i = t; i < BATCH * DHEAD * DHEAD; i += stride) g_ctxT[i] = 0.0f;
    for (int i = t; i < BATCH * DHEAD; i += stride) g_rs[i] = 0.0f;
    for (int i = t; i < MQ; i += stride) {
        float s = gq[i] * rsqrtf(vq[i] + eps); g_bq[i] = bq[i] - mq[i] * s;
    }
    for (int i = t; i < CIN; i += stride) {
        float s = gp[i] * rsqrtf(vp[i] + eps); g_bp[i] = bp[i] - mp[i] * s;
    }
    for (int i = t; i < DHEAD; i += stride) {
        float s = gkv[i] * rsqrtf(vkv[i] + eps); g_bkv[i] = bkv[i] - mkv[i] * s;
    }
    for (int i = t; i < DHEAD * CIN; i += stride) {
        int o = i / CIN; g_Wkv[i] = Wkv[i] * gkv[o] * rsqrtf(vkv[o] + eps);
    }
    for (int i = t; i < MQ * CIN; i += stride) {
        int m = i >> 8;
        g_WH[0][i] = __float2half_rn(Wq[i] * gq[m] * rsqrtf(vq[m] + eps));
        g_WH[1][i] = __float2half_rn(Wp[i] * gp[m] * rsqrtf(vp[m] + eps));
    }
}

// ---------------- 2) FUSED kv + ctx (R14 form, unchanged) ------------------------
__global__ __launch_bounds__(256) void kvctx_kernel(const float* __restrict__ X)
{
    __shared__ __align__(16) float Ws[CIN][DHEAD];
    __shared__ float bs[DHEAD];
    __shared__ float kvs[DHEAD][129];
    __shared__ float ps [DHEAD][129];

    int t = threadIdx.x;
    for (int i = t; i < DHEAD * CIN; i += 256) {
        int m = i / CIN, k = i % CIN;
        Ws[k][m] = g_Wkv[i];
    }
    if (t < DHEAD) bs[t] = g_bkv[t];
    __syncthreads();

    int b = blockIdx.y;
    int n = blockIdx.x * 256 + t;
    const float* x = X + (size_t)b * CIN * HWN + n;
    __half* xin = g_XIN + (size_t)b * CIN * HWN + n;

    unsigned long long acc[16];
#pragma unroll
    for (int j = 0; j < 16; j++) PACKF2(acc[j], bs[2 * j], bs[2 * j + 1]);

#pragma unroll 4
    for (int k = 0; k < CIN; k++) {
        float xv = x[(size_t)k * HWN];
        xin[(size_t)k * HWN] = __float2half_rn(xv);
        unsigned long long xp; PACKF2(xp, xv, xv);
        const ulonglong2* wr = reinterpret_cast<const ulonglong2*>(&Ws[k][0]);
#pragma unroll
        for (int j = 0; j < 8; j++) {
            ulonglong2 w = wr[j];
            FMAF2(acc[2 * j],     w.x, xp);
            FMAF2(acc[2 * j + 1], w.y, xp);
        }
    }

    float kvf[32];
#pragma unroll
    for (int j = 0; j < 16; j++) UNPACKF2(kvf[2 * j], kvf[2 * j + 1], acc[j]);

    int d = t & 31, e0 = (t >> 5) * 4;
    int half_id = t >> 7, pos = t & 127;
    float cacc[4] = {0.f, 0.f, 0.f, 0.f};
    float srow = 0.0f;
    int r = t >> 3, seg = t & 7;

    for (int h = 0; h < 2; h++) {
        __syncthreads();
        if (half_id == h) {
#pragma unroll
            for (int j = 0; j < 32; j++) {
                kvs[j][pos] = kvf[j];
                ps [j][pos] = __expf(kvf[j]);
            }
        }
        __syncthreads();
#pragma unroll 4
        for (int q = 0; q < 16; q++) srow += ps[r][seg * 16 + q];
#pragma unroll 4
        for (int nn = 0; nn < 128; nn++) {
            float kd = kvs[d][nn];
#pragma unroll
            for (int j = 0; j < 4; j++) cacc[j] += ps[e0 + j][nn] * kd;
        }
    }

#pragma unroll
    for (int o = 4; o > 0; o >>= 1) srow += __shfl_xor_sync(~0u, srow, o);
    if (seg == 0) atomicAdd(&g_rs[b * DHEAD + r], srow);
#pragma unroll
    for (int j = 0; j < 4; j++)
        atomicAdd(&g_ctxT[b * 1024 + d * 32 + (e0 + j)], cacc[j]);
}

// ---------------- 3) FUSED qattn+proj: 1024 thr / 32 warps (8x4), M=256, N=128 ----
// smem layout:
//   [0, 73728)        Wq stages (2 x 36864); after GEMM0, sQ/XF (256 x 136 halves)
//   [73728, 108544)   X stages (2 x 17408)
//   [108544, 182272)  Wp stages (2 x 36864)
//   [182272, 187392)  ctxT hi/lo (2 x 2560)
//   [187392, 188416)  bias q (256 floats)
#define FZ_W0   0
#define FZ_W1   36864
#define FZ_X0   73728
#define FZ_X1   91136
#define FZ_P0   108544
#define FZ_P1   145408
#define FZ_CSH  182272
#define FZ_CSL  184832
#define FZ_BQ   187392
#define FZ_SMEM 188416
#define FZ_Q    0

__global__ void __launch_bounds__(1024, 1) fused_kernel(float* __restrict__ out)
{
    extern __shared__ __align__(16) char smem[];
    __half* sCh = reinterpret_cast<__half*>(smem + FZ_CSH);
    __half* sCl = reinterpret_cast<__half*>(smem + FZ_CSL);
    float* sBias = reinterpret_cast<float*>(smem + FZ_BQ);
    __half* sQ  = reinterpret_cast<__half*>(smem + FZ_Q);
    uint32_t sb = (uint32_t)__cvta_generic_to_shared(smem);

    int t = threadIdx.x, lane = t & 31, wid = t >> 5;
    int wm = wid >> 2, wn = wid & 3;     // 8 x 4 warp grid; head = wm
    int nt = blockIdx.x, b = blockIdx.y;
    int n0 = nt * 128;
    const __half* W  = g_WH[0];
    const __half* Wp = g_WH[1];
    const __half* Xin = g_XIN + (size_t)b * CIN * HWN + n0;

    // preload ctxT (deferred normalization) + bias
    {
        int d = t >> 5, e = t & 31;      // t < 1024 exactly
        float f = g_ctxT[b * 1024 + t] / g_rs[b * DHEAD + e];
        __half h = __float2half_rn(f);
        sCh[d * 40 + e] = h;
        sCl[d * 40 + e] = __float2half_rn(f - __half2float(h));
    }
    if (t < 256) sBias[t] = g_bq[t];

    // ---- prologue: chunk 0 (W: 256x64, X: 64x128) ----
#pragma unroll
    for (int i = 0; i < 2; i++) {
        int j = t + i * 1024;
        int row = j >> 3, seg = j & 7;
        cp16(sb + FZ_W0 + (uint32_t)(row * 72 + seg * 8) * 2,
             W + (size_t)row * CIN + seg * 8);
    }
    {
        int k = t >> 4, seg = t & 15;
        cp16(sb + FZ_X0 + (uint32_t)(k * 136 + seg * 8) * 2,
             Xin + (size_t)k * HWN + seg * 8);
    }
    CP_COMMIT();
    CP_WAIT0();
    __syncthreads();

    float acc[2][4][4];
#pragma unroll
    for (int i = 0; i < 2; i++)
#pragma unroll
        for (int j = 0; j < 4; j++)
#pragma unroll
            for (int k = 0; k < 4; k++) acc[i][j][k] = 0.0f;

    // ---- GEMM0 mainloop: 4 K-chunks, double-buffered ----
    for (int c = 0; c < 4; c++) {
        int s = c & 1;
        uint32_t wbase = sb + (s ? FZ_W1 : FZ_W0);
        uint32_t xbase = sb + (s ? FZ_X1 : FZ_X0);
        if (c < 3) {
            int k0n = (c + 1) * 64;
            uint32_t wdst = sb + (s ? FZ_W0 : FZ_W1);
            uint32_t xdst = sb + (s ? FZ_X0 : FZ_X1);
#pragma unroll
            for (int i = 0; i < 2; i++) {
                int j = t + i * 1024;
                int row = j >> 3, seg = j & 7;
                cp16(wdst + (uint32_t)(row * 72 + seg * 8) * 2,
                     W + (size_t)row * CIN + k0n + seg * 8);
            }
            {
                int k = t >> 4, seg = t & 15;
                cp16(xdst + (uint32_t)(k * 136 + seg * 8) * 2,
                     Xin + (size_t)(k0n + k) * HWN + seg * 8);
            }
            CP_COMMIT();
        }
#pragma unroll
        for (int ks = 0; ks < 4; ks++) {
            int kk = ks * 16;
            uint32_t ah[2][4];
#pragma unroll
            for (int mf = 0; mf < 2; mf++) {
                int row = wm * 32 + mf * 16 + (lane & 15);
                int col = kk + (lane >> 4) * 8;
                ldsm4(ah[mf], wbase + (uint32_t)(row * 72 + col) * 2);
            }
#pragma unroll
            for (int r = 0; r < 2; r++) {
                int kr = kk + (lane & 15);
                int coln = wn * 32 + r * 16 + (lane >> 4) * 8;
                uint32_t bh[4];
                ldsm4t(bh, xbase + (uint32_t)(kr * 136 + coln) * 2);
#pragma unroll
                for (int mf = 0; mf < 2; mf++) {
                    mma_f16(acc[mf][r * 2],     ah[mf], bh[0], bh[1]);
                    mma_f16(acc[mf][r * 2 + 1], ah[mf], bh[2], bh[3]);
                }
            }
        }
        if (c < 3) {
            CP_WAIT0();
            __syncthreads();
        }
    }
    __syncthreads();   // all GEMM0 compute done before sQ overwrites W stages

    // kick off Wp chunk 0 load early (dedicated region) — overlaps attn epilogue
#pragma unroll
    for (int i = 0; i < 2; i++) {
        int j = t + i * 1024;
        int row = j >> 3, seg = j & 7;
        cp16(sb + FZ_P0 + (uint32_t)(row * 72 + seg * 8) * 2,
             Wp + (size_t)row * CIN + seg * 8);
    }
    CP_COMMIT();

    // ---- bias + per-column head softmax (head = wm) ----
    {
        int r0 = wm * 32 + (lane >> 2);
        float bv[4] = { sBias[r0], sBias[r0 + 8], sBias[r0 + 16], sBias[r0 + 24] };
#pragma unroll
        for (int mf = 0; mf < 2; mf++)
#pragma unroll
            for (int nf = 0; nf < 4; nf++)
#pragma unroll
                for (int k = 0; k < 4; k++)
                    acc[mf][nf][k] += bv[mf * 2 + (k >> 1)];
    }
#pragma unroll
    for (int nf = 0; nf < 4; nf++) {
#pragma unroll
        for (int p = 0; p < 2; p++) {
            float m = fmaxf(fmaxf(acc[0][nf][p], acc[0][nf][p + 2]),
                            fmaxf(acc[1][nf][p], acc[1][nf][p + 2]));
            m = fmaxf(m, __shfl_xor_sync(~0u, m, 4));
            m = fmaxf(m, __shfl_xor_sync(~0u, m, 8));
            m = fmaxf(m, __shfl_xor_sync(~0u, m, 16));
            float e00 = __expf(acc[0][nf][p] - m);
            float e01 = __expf(acc[0][nf][p + 2] - m);
            float e10 = __expf(acc[1][nf][p] - m);
            float e11 = __expf(acc[1][nf][p + 2] - m);
            float s = e00 + e01 + e10 + e11;
            s += __shfl_xor_sync(~0u, s, 4);
            s += __shfl_xor_sync(~0u, s, 8);
            s += __shfl_xor_sync(~0u, s, 16);
            float inv = 1.0f / s;
            acc[0][nf][p]     = e00 * inv;
            acc[0][nf][p + 2] = e01 * inv;
            acc[1][nf][p]     = e10 * inv;
            acc[1][nf][p + 2] = e11 * inv;
        }
    }
    // stage softmaxed q (rows wm*32.., cols wn*32.., stride 136)
#pragma unroll
    for (int mf = 0; mf < 2; mf++)
#pragma unroll
        for (int nf = 0; nf < 4; nf++) {
            int row = wm * 32 + mf * 16 + (lane >> 2);
            int col = wn * 32 + nf * 8 + (lane & 3) * 2;
            *reinterpret_cast<uint32_t*>(sQ + row * 136 + col) =
                packh2(__float2half_rn(acc[0 + (mf & 1)][nf][0]), __float2half_rn(acc[mf][nf][1]));
            *reinterpret_cast<uint32_t*>(sQ + (row + 8) * 136 + col) =
                packh2(__float2half_rn(acc[mf][nf][2]), __float2half_rn(acc[mf][nf][3]));
        }
    __syncwarp();

    // ---- att = ctxT @ q (ctxT hi/lo 2-pass), in-register ----
    float att[2][4][4];
#pragma unroll
    for (int i = 0; i < 2; i++)
#pragma unroll
        for (int j = 0; j < 4; j++)
#pragma unroll
            for (int k = 0; k < 4; k++) att[i][j][k] = 0.0f;

#pragma unroll
    for (int kf = 0; kf < 2; kf++) {
        uint32_t ach[2][4], acl[2][4];
#pragma unroll
        for (int mf = 0; mf < 2; mf++) {
            int row = mf * 16 + (lane & 15);
            int col = kf * 16 + (lane >> 4) * 8;
            uint32_t a_addr = sb + FZ_CSH + (uint32_t)(row * 40 + col) * 2;
            ldsm4(ach[mf], a_addr);
            ldsm4(acl[mf], a_addr + (FZ_CSL - FZ_CSH));
        }
#pragma unroll
        for (int r = 0; r < 2; r++) {
            int kr = wm * 32 + kf * 16 + (lane & 15);
            int coln = wn * 32 + r * 16 + (lane >> 4) * 8;
            uint32_t qb[4];
            ldsm4t(qb, sb + FZ_Q + (uint32_t)(kr * 136 + coln) * 2);
#pragma unroll
            for (int mf = 0; mf < 2; mf++) {
                mma_f16(att[mf][r * 2],     ach[mf], qb[0], qb[1]);
                mma_f16(att[mf][r * 2 + 1], ach[mf], qb[2], qb[3]);
                mma_f16(att[mf][r * 2],     acl[mf], qb[0], qb[1]);
                mma_f16(att[mf][r * 2 + 1], acl[mf], qb[2], qb[3]);
            }
        }
    }

    // relu + overwrite sQ in place (same rows/cols block) -> XF smem
#pragma unroll
    for (int mf = 0; mf < 2; mf++)
#pragma unroll
        for (int nf = 0; nf < 4; nf++) {
            int row = wm * 32 + mf * 16 + (lane >> 2);
            int col = wn * 32 + nf * 8 + (lane & 3) * 2;
            float v0 = fmaxf(att[mf][nf][0], 0.f), v1 = fmaxf(att[mf][nf][1], 0.f);
            float v2 = fmaxf(att[mf][nf][2], 0.f), v3 = fmaxf(att[mf][nf][3], 0.f);
            *reinterpret_cast<uint32_t*>(sQ + row * 136 + col) =
                packh2(__float2half_rn(v0), __float2half_rn(v1));
            *reinterpret_cast<uint32_t*>(sQ + (row + 8) * 136 + col) =
                packh2(__float2half_rn(v2), __float2half_rn(v3));
        }
    CP_WAIT0();        // Wp chunk 0 landed
    __syncthreads();   // all warps' XF blocks visible

    // ---- proj mainloop: out = Wp @ XF + bp;  B = XF smem (rows 0..255, stride 136)
    float acc2[2][4][4];
#pragma unroll
    for (int i = 0; i < 2; i++)
#pragma unroll
        for (int j = 0; j < 4; j++)
#pragma unroll
            for (int k = 0; k < 4; k++) acc2[i][j][k] = 0.0f;

    for (int c = 0; c < 4; c++) {
        int s = c & 1;
        uint32_t wbase = sb + (s ? FZ_P1 : FZ_P0);
        if (c < 3) {
            int k0n = (c + 1) * 64;
            uint32_t wdst = sb + (s ? FZ_P0 : FZ_P1);
#pragma unroll
            for (int i = 0; i < 2; i++) {
                int j = t + i * 1024;
                int row = j >> 3, seg = j & 7;
                cp16(wdst + (uint32_t)(row * 72 + seg * 8) * 2,
                     Wp + (size_t)row * CIN + k0n + seg * 8);
            }
            CP_COMMIT();
        }
#pragma unroll
        for (int ks = 0; ks < 4; ks++) {
            int kk = ks * 16;
            uint32_t ah[2][4];
#pragma unroll
            for (int mf = 0; mf < 2; mf++) {
                int row = wm * 32 + mf * 16 + (lane & 15);
                int col = kk + (lane >> 4) * 8;
                ldsm4(ah[mf], wbase + (uint32_t)(row * 72 + col) * 2);
            }
#pragma unroll
            for (int r = 0; r < 2; r++) {
                int kr = c * 64 + kk + (lane & 15);
                int coln = wn * 32 + r * 16 + (lane >> 4) * 8;
                uint32_t bh[4];
                ldsm4t(bh, sb + FZ_Q + (uint32_t)(kr * 136 + coln) * 2);
#pragma unroll
                for (int mf = 0; mf < 2; mf++) {
                    mma_f16(acc2[mf][r * 2],     ah[mf], bh[0], bh[1]);
                    mma_f16(acc2[mf][r * 2 + 1], ah[mf], bh[2], bh[3]);
                }
            }
        }
        if (c < 3) CP_WAIT0();   // Wp stages are warp-read-only; no barrier needed
        __syncthreads();          // but stage reuse requires all warps done reading
    }

    // ---- epilogue: bias + fp32 store ----
    int r0 = wm * 32 + (lane >> 2);
    float bv[4] = { g_bp[r0], g_bp[r0 + 8], g_bp[r0 + 16], g_bp[r0 + 24] };
#pragma unroll
    for (int mf = 0; mf < 2; mf++)
#pragma unroll
        for (int nf = 0; nf < 4; nf++) {
            int row = wm * 32 + mf * 16 + (lane >> 2);
            int col = n0 + wn * 32 + nf * 8 + (lane & 3) * 2;
            float bb0 = bv[mf * 2], bb1 = bv[mf * 2 + 1];
            *reinterpret_cast<float2*>(&out[((size_t)(b * MQ) + row) * HWN + col]) =
                make_float2(acc2[mf][nf][0] + bb0, acc2[mf][nf][1] + bb0);
            *reinterpret_cast<float2*>(&out[((size_t)(b * MQ) + row + 8) * HWN + col]) =
                make_float2(acc2[mf][nf][2] + bb1, acc2[mf][nf][3] + bb1);
        }
}

// ---------------- launch ------------------------------------------------------------
extern "C" void kernel_launch(void* const* d_in, const int* in_sizes, int n_in,
                              void* d_out, int out_size)
{
    const float* input = (const float*)d_in[0];
    const float* Wq  = (const float*)d_in[2];
    const float* gq  = (const float*)d_in[3];
    const float* bq  = (const float*)d_in[4];
    const float* mq  = (const float*)d_in[5];
    const float* vq  = (const float*)d_in[6];
    const float* Wkv = (const float*)d_in[7];
    const float* gkv = (const float*)d_in[8];
    const float* bkv = (const float*)d_in[9];
    const float* mkv = (const float*)d_in[10];
    const float* vkv = (const float*)d_in[11];
    const float* Wp  = (const float*)d_in[12];
    const float* gp  = (const float*)d_in[13];
    const float* bp  = (const float*)d_in[14];
    const float* mp  = (const float*)d_in[15];
    const float* vp  = (const float*)d_in[16];
    float* out = (float*)d_out;

    cudaFuncSetAttribute(fused_kernel, cudaFuncAttributeMaxDynamicSharedMemorySize,
                         FZ_SMEM);

    fold_kernel<<<64, 256>>>(Wq, gq, bq, mq, vq,
                             Wkv, gkv, bkv, mkv, vkv,
                             Wp, gp, bp, mp, vp);
    kvctx_kernel<<<dim3(HWN / 256, BATCH), 256>>>(input);
    fused_kernel<<<dim3(HWN / 128, BATCH), 1024, FZ_SMEM>>>(out);
}

// round 16
// speedup vs baseline: 1.1279x; 1.1279x over previous
#include <cuda_runtime.h>
#include <cuda_fp16.h>
#include <cstdint>

#define BATCH 16
#define CIN   256
#define HWN   4096
#define DHEAD 32
#define NHEAD 8
#define MQ    256

// ---------------- scratch (device globals) -----------------------------------
__device__ float g_ctxT[BATCH * DHEAD * DHEAD];   // UNNORMALIZED ctxT'
__device__ float g_rs[BATCH * DHEAD];             // row exp-sums S_e
__device__ float g_Wkv[DHEAD * CIN]; __device__ float g_bkv[DHEAD];
__device__ float g_bq [MQ];          __device__ float g_bp [CIN];
__device__ __half g_WH[2][MQ * CIN];
__device__ __half g_XIN[(size_t)BATCH * CIN * HWN];
__device__ __half g_XF[(size_t)BATCH * MQ * HWN];

// ---------------- f32x2 helpers ------------------------------------------------
#define PACKF2(u, lo, hi) asm("mov.b64 %0, {%1, %2};" : "=l"(u) : "f"(lo), "f"(hi))
#define UNPACKF2(lo, hi, u) asm("mov.b64 {%0, %1}, %2;" : "=f"(lo), "=f"(hi) : "l"(u))
#define FMAF2(c, a, b) asm("fma.rn.f32x2 %0, %1, %2, %0;" : "+l"(c) : "l"(a), "l"(b))

// ---------------- mma / async helpers -------------------------------------------
__device__ __forceinline__ void ldsm4(uint32_t* r, uint32_t addr) {
    asm volatile("ldmatrix.sync.aligned.m8n8.x4.shared.b16 {%0,%1,%2,%3}, [%4];\n"
        : "=r"(r[0]), "=r"(r[1]), "=r"(r[2]), "=r"(r[3]) : "r"(addr));
}
__device__ __forceinline__ void ldsm4t(uint32_t* r, uint32_t addr) {
    asm volatile("ldmatrix.sync.aligned.m8n8.x4.trans.shared.b16 {%0,%1,%2,%3}, [%4];\n"
        : "=r"(r[0]), "=r"(r[1]), "=r"(r[2]), "=r"(r[3]) : "r"(addr));
}
__device__ __forceinline__ void mma_f16(float* c, const uint32_t* a,
                                        uint32_t b0, uint32_t b1) {
    asm volatile(
        "mma.sync.aligned.m16n8k16.row.col.f32.f16.f16.f32 "
        "{%0,%1,%2,%3}, {%4,%5,%6,%7}, {%8,%9}, {%0,%1,%2,%3};\n"
        : "+f"(c[0]), "+f"(c[1]), "+f"(c[2]), "+f"(c[3])
        : "r"(a[0]), "r"(a[1]), "r"(a[2]), "r"(a[3]), "r"(b0), "r"(b1));
}
__device__ __forceinline__ uint32_t packh2(__half a, __half b) {
    return (uint32_t)__half_as_ushort(a) | ((uint32_t)__half_as_ushort(b) << 16);
}
__device__ __forceinline__ void cp16(uint32_t saddr, const void* gptr) {
    asm volatile("cp.async.cg.shared.global [%0], [%1], 16;" :: "r"(saddr), "l"(gptr));
}
#define CP_COMMIT() asm volatile("cp.async.commit_group;" ::: "memory")
#define CP_WAIT0()  asm volatile("cp.async.wait_group 0;" ::: "memory")

// ---------------- 1) fold BN + fp16 weight plane + zero accumulators -----------
// grid 512 x 256 thr: full-chip parallelism for this tiny latency-bound kernel.
__global__ void fold_kernel(
    const float* __restrict__ Wq, const float* __restrict__ gq, const float* __restrict__ bq,
    const float* __restrict__ mq, const float* __restrict__ vq,
    const float* __restrict__ Wkv, const float* __restrict__ gkv, const float* __restrict__ bkv,
    const float* __restrict__ mkv, const float* __restrict__ vkv,
    const float* __restrict__ Wp, const float* __restrict__ gp, const float* __restrict__ bp,
    const float* __restrict__ mp, const float* __restrict__ vp)
{
    int t = blockIdx.x * blockDim.x + threadIdx.x;
    int stride = gridDim.x * blockDim.x;
    const float eps = 1e-5f;
    for (int i = t; i < BATCH * DHEAD * DHEAD; i += stride) g_ctxT[i] = 0.0f;
    for (int i = t; i < BATCH * DHEAD; i += stride) g_rs[i] = 0.0f;
    for (int i = t; i < MQ; i += stride) {
        float s = gq[i] * rsqrtf(vq[i] + eps); g_bq[i] = bq[i] - mq[i] * s;
    }
    for (int i = t; i < CIN; i += stride) {
        float s = gp[i] * rsqrtf(vp[i] + eps); g_bp[i] = bp[i] - mp[i] * s;
    }
    for (int i = t; i < DHEAD; i += stride) {
        float s = gkv[i] * rsqrtf(vkv[i] + eps); g_bkv[i] = bkv[i] - mkv[i] * s;
    }
    for (int i = t; i < DHEAD * CIN; i += stride) {
        int o = i / CIN; g_Wkv[i] = Wkv[i] * gkv[o] * rsqrtf(vkv[o] + eps);
    }
    for (int i = t; i < MQ * CIN; i += stride) {
        int m = i >> 8;
        g_WH[0][i] = __float2half_rn(Wq[i] * gq[m] * rsqrtf(vq[m] + eps));
        g_WH[1][i] = __float2half_rn(Wp[i] * gp[m] * rsqrtf(vp[m] + eps));
    }
}

// ---------------- 2) FUSED kv + ctx (R14 form, unchanged) ------------------------
__global__ __launch_bounds__(256) void kvctx_kernel(const float* __restrict__ X)
{
    __shared__ __align__(16) float Ws[CIN][DHEAD];
    __shared__ float bs[DHEAD];
    __shared__ float kvs[DHEAD][129];
    __shared__ float ps [DHEAD][129];

    int t = threadIdx.x;
    for (int i = t; i < DHEAD * CIN; i += 256) {
        int m = i / CIN, k = i % CIN;
        Ws[k][m] = g_Wkv[i];
    }
    if (t < DHEAD) bs[t] = g_bkv[t];
    __syncthreads();

    int b = blockIdx.y;
    int n = blockIdx.x * 256 + t;
    const float* x = X + (size_t)b * CIN * HWN + n;
    __half* xin = g_XIN + (size_t)b * CIN * HWN + n;

    unsigned long long acc[16];
#pragma unroll
    for (int j = 0; j < 16; j++) PACKF2(acc[j], bs[2 * j], bs[2 * j + 1]);

#pragma unroll 4
    for (int k = 0; k < CIN; k++) {
        float xv = x[(size_t)k * HWN];
        xin[(size_t)k * HWN] = __float2half_rn(xv);
        unsigned long long xp; PACKF2(xp, xv, xv);
        const ulonglong2* wr = reinterpret_cast<const ulonglong2*>(&Ws[k][0]);
#pragma unroll
        for (int j = 0; j < 8; j++) {
            ulonglong2 w = wr[j];
            FMAF2(acc[2 * j],     w.x, xp);
            FMAF2(acc[2 * j + 1], w.y, xp);
        }
    }

    float kvf[32];
#pragma unroll
    for (int j = 0; j < 16; j++) UNPACKF2(kvf[2 * j], kvf[2 * j + 1], acc[j]);

    int d = t & 31, e0 = (t >> 5) * 4;
    int half_id = t >> 7, pos = t & 127;
    float cacc[4] = {0.f, 0.f, 0.f, 0.f};
    float srow = 0.0f;
    int r = t >> 3, seg = t & 7;

    for (int h = 0; h < 2; h++) {
        __syncthreads();
        if (half_id == h) {
#pragma unroll
            for (int j = 0; j < 32; j++) {
                kvs[j][pos] = kvf[j];
                ps [j][pos] = __expf(kvf[j]);
            }
        }
        __syncthreads();
#pragma unroll 4
        for (int q = 0; q < 16; q++) srow += ps[r][seg * 16 + q];
#pragma unroll 4
        for (int nn = 0; nn < 128; nn++) {
            float kd = kvs[d][nn];
#pragma unroll
            for (int j = 0; j < 4; j++) cacc[j] += ps[e0 + j][nn] * kd;
        }
    }

#pragma unroll
    for (int o = 4; o > 0; o >>= 1) srow += __shfl_xor_sync(~0u, srow, o);
    if (seg == 0) atomicAdd(&g_rs[b * DHEAD + r], srow);
#pragma unroll
    for (int j = 0; j < 4; j++)
        atomicAdd(&g_ctxT[b * 1024 + d * 32 + (e0 + j)], cacc[j]);
}

// ---------------- 3) qattn: 512 thr / 16 warps / warp tile 32x32 (R11 config) -----
#define QA_WS0  0
#define QA_WS1  18432
#define QA_XS0  36864
#define QA_XS1  54272
#define QA_CSH  71680
#define QA_CSL  74240
#define QA_BIAS 76800
#define QA_SMEM 77312
#define QA_Q    0

__global__ void __launch_bounds__(512, 2) qattn_kernel()
{
    extern __shared__ __align__(16) char smem[];
    __half* sCh = reinterpret_cast<__half*>(smem + QA_CSH);
    __half* sCl = reinterpret_cast<__half*>(smem + QA_CSL);
    float* sBias = reinterpret_cast<float*>(smem + QA_BIAS);
    __half* sQ  = reinterpret_cast<__half*>(smem + QA_Q);
    uint32_t sb = (uint32_t)__cvta_generic_to_shared(smem);

    int t = threadIdx.x, lane = t & 31, wid = t >> 5;
    int wm = wid >> 2, wn = wid & 3;
    int nt = blockIdx.x, mt = blockIdx.y, b = blockIdx.z;
    int n0 = nt * 128, m0 = mt * 128;
    const __half* W = g_WH[0] + (size_t)m0 * CIN;
    const __half* Xin = g_XIN + (size_t)b * CIN * HWN + n0;

    for (int i = t; i < 1024; i += 512) {
        int d = i >> 5, e = i & 31;
        float f = g_ctxT[b * 1024 + i] / g_rs[b * DHEAD + e];
        __half h = __float2half_rn(f);
        sCh[d * 40 + e] = h;
        sCl[d * 40 + e] = __float2half_rn(f - __half2float(h));
    }
    if (t < 128) sBias[t] = g_bq[m0 + t];

#pragma unroll
    for (int i = 0; i < 2; i++) {
        int j = t + i * 512;
        int row = j >> 3, seg = j & 7;
        cp16(sb + QA_WS0 + (uint32_t)(row * 72 + seg * 8) * 2,
             W + (size_t)row * CIN + seg * 8);
    }
#pragma unroll
    for (int i = 0; i < 2; i++) {
        int j = t + i * 512;
        int k = j >> 4, seg = j & 15;
        cp16(sb + QA_XS0 + (uint32_t)(k * 136 + seg * 8) * 2,
             Xin + (size_t)k * HWN + seg * 8);
    }
    CP_COMMIT();
    CP_WAIT0();
    __syncthreads();

    float acc[2][4][4];
#pragma unroll
    for (int i = 0; i < 2; i++)
#pragma unroll
        for (int j = 0; j < 4; j++)
#pragma unroll
            for (int k = 0; k < 4; k++) acc[i][j][k] = 0.0f;

    for (int c = 0; c < 4; c++) {
        int s = c & 1;
        uint32_t wbase = sb + (s ? QA_WS1 : QA_WS0);
        uint32_t xbase = sb + (s ? QA_XS1 : QA_XS0);
        if (c < 3) {
            int k0n = (c + 1) * 64;
            uint32_t wdst = sb + (s ? QA_WS0 : QA_WS1);
            uint32_t xdst = sb + (s ? QA_XS0 : QA_XS1);
#pragma unroll
            for (int i = 0; i < 2; i++) {
                int j = t + i * 512;
                int row = j >> 3, seg = j & 7;
                cp16(wdst + (uint32_t)(row * 72 + seg * 8) * 2,
                     W + (size_t)row * CIN + k0n + seg * 8);
            }
#pragma unroll
            for (int i = 0; i < 2; i++) {
                int j = t + i * 512;
                int k = j >> 4, seg = j & 15;
                cp16(xdst + (uint32_t)(k * 136 + seg * 8) * 2,
                     Xin + (size_t)(k0n + k) * HWN + seg * 8);
            }
            CP_COMMIT();
        }
#pragma unroll
        for (int ks = 0; ks < 4; ks++) {
            int kk = ks * 16;
            uint32_t ah[2][4];
#pragma unroll
            for (int mf = 0; mf < 2; mf++) {
                int row = wm * 32 + mf * 16 + (lane & 15);
                int col = kk + (lane >> 4) * 8;
                ldsm4(ah[mf], wbase + (uint32_t)(row * 72 + col) * 2);
            }
#pragma unroll
            for (int r = 0; r < 2; r++) {
                int kr = kk + (lane & 15);
                int coln = wn * 32 + r * 16 + (lane >> 4) * 8;
                uint32_t bh[4];
                ldsm4t(bh, xbase + (uint32_t)(kr * 136 + coln) * 2);
#pragma unroll
                for (int mf = 0; mf < 2; mf++) {
                    mma_f16(acc[mf][r * 2],     ah[mf], bh[0], bh[1]);
                    mma_f16(acc[mf][r * 2 + 1], ah[mf], bh[2], bh[3]);
                }
            }
        }
        if (c < 3) {
            CP_WAIT0();
            __syncthreads();
        }
    }
    __syncthreads();

    {
        int r0 = wm * 32 + (lane >> 2);
        float bv[4] = { sBias[r0], sBias[r0 + 8], sBias[r0 + 16], sBias[r0 + 24] };
#pragma unroll
        for (int mf = 0; mf < 2; mf++)
#pragma unroll
            for (int nf = 0; nf < 4; nf++)
#pragma unroll
                for (int k = 0; k < 4; k++)
                    acc[mf][nf][k] += bv[mf * 2 + (k >> 1)];
    }
#pragma unroll
    for (int nf = 0; nf < 4; nf++) {
#pragma unroll
        for (int p = 0; p < 2; p++) {
            float m = fmaxf(fmaxf(acc[0][nf][p], acc[0][nf][p + 2]),
                            fmaxf(acc[1][nf][p], acc[1][nf][p + 2]));
            m = fmaxf(m, __shfl_xor_sync(~0u, m, 4));
            m = fmaxf(m, __shfl_xor_sync(~0u, m, 8));
            m = fmaxf(m, __shfl_xor_sync(~0u, m, 16));
            float e00 = __expf(acc[0][nf][p] - m);
            float e01 = __expf(acc[0][nf][p + 2] - m);
            float e10 = __expf(acc[1][nf][p] - m);
            float e11 = __expf(acc[1][nf][p + 2] - m);
            float s = e00 + e01 + e10 + e11;
            s += __shfl_xor_sync(~0u, s, 4);
            s += __shfl_xor_sync(~0u, s, 8);
            s += __shfl_xor_sync(~0u, s, 16);
            float inv = 1.0f / s;
            acc[0][nf][p]     = e00 * inv;
            acc[0][nf][p + 2] = e01 * inv;
            acc[1][nf][p]     = e10 * inv;
            acc[1][nf][p + 2] = e11 * inv;
        }
    }
#pragma unroll
    for (int mf = 0; mf < 2; mf++)
#pragma unroll
        for (int nf = 0; nf < 4; nf++) {
            int row = wm * 32 + mf * 16 + (lane >> 2);
            int col = wn * 32 + nf * 8 + (lane & 3) * 2;
            *reinterpret_cast<uint32_t*>(sQ + row * 136 + col) =
                packh2(__float2half_rn(acc[mf][nf][0]), __float2half_rn(acc[mf][nf][1]));
            *reinterpret_cast<uint32_t*>(sQ + (row + 8) * 136 + col) =
                packh2(__float2half_rn(acc[mf][nf][2]), __float2half_rn(acc[mf][nf][3]));
        }
    __syncwarp();

    float att[2][4][4];
#pragma unroll
    for (int i = 0; i < 2; i++)
#pragma unroll
        for (int j = 0; j < 4; j++)
#pragma unroll
            for (int k = 0; k < 4; k++) att[i][j][k] = 0.0f;

#pragma unroll
    for (int kf = 0; kf < 2; kf++) {
        uint32_t ach[2][4], acl[2][4];
#pragma unroll
        for (int mf = 0; mf < 2; mf++) {
            int row = mf * 16 + (lane & 15);
            int col = kf * 16 + (lane >> 4) * 8;
            uint32_t a_addr = sb + QA_CSH + (uint32_t)(row * 40 + col) * 2;
            ldsm4(ach[mf], a_addr);
            ldsm4(acl[mf], a_addr + (QA_CSL - QA_CSH));
        }
#pragma unroll
        for (int r = 0; r < 2; r++) {
            int kr = wm * 32 + kf * 16 + (lane & 15);
            int coln = wn * 32 + r * 16 + (lane >> 4) * 8;
            uint32_t qb[4];
            ldsm4t(qb, sb + QA_Q + (uint32_t)(kr * 136 + coln) * 2);
#pragma unroll
            for (int mf = 0; mf < 2; mf++) {
                mma_f16(att[mf][r * 2],     ach[mf], qb[0], qb[1]);
                mma_f16(att[mf][r * 2 + 1], ach[mf], qb[2], qb[3]);
                mma_f16(att[mf][r * 2],     acl[mf], qb[0], qb[1]);
                mma_f16(att[mf][r * 2 + 1], acl[mf], qb[2], qb[3]);
            }
        }
    }

#pragma unroll
    for (int mf = 0; mf < 2; mf++)
#pragma unroll
        for (int nf = 0; nf < 4; nf++) {
            int row = m0 + wm * 32 + mf * 16 + (lane >> 2);
            int col = n0 + wn * 32 + nf * 8 + (lane & 3) * 2;
            float v0 = fmaxf(att[mf][nf][0], 0.f), v1 = fmaxf(att[mf][nf][1], 0.f);
            float v2 = fmaxf(att[mf][nf][2], 0.f), v3 = fmaxf(att[mf][nf][3], 0.f);
            *reinterpret_cast<uint32_t*>(&g_XF[((size_t)(b * MQ) + row) * HWN + col]) =
                packh2(__float2half_rn(v0), __float2half_rn(v1));
            *reinterpret_cast<uint32_t*>(&g_XF[((size_t)(b * MQ) + row + 8) * HWN + col]) =
                packh2(__float2half_rn(v2), __float2half_rn(v3));
        }
}

// ---------------- 4) proj: 512 thr / 16 warps / warp tile 32x32 (R11 config) ------
#define G1_WS0  0
#define G1_WS1  18432
#define G1_XS0  36864
#define G1_XS1  54272
#define G1_SMEM 71680

__global__ void __launch_bounds__(512, 2) proj_kernel(float* __restrict__ out)
{
    extern __shared__ __align__(16) char smem[];
    uint32_t sb = (uint32_t)__cvta_generic_to_shared(smem);

    int t = threadIdx.x, lane = t & 31, wid = t >> 5;
    int wm = wid >> 2, wn = wid & 3;
    int nt = blockIdx.x, mt = blockIdx.y, b = blockIdx.z;
    int n0 = nt * 128, m0 = mt * 128;
    const __half* W = g_WH[1] + (size_t)m0 * CIN;
    const __half* Xin = g_XF + (size_t)b * MQ * HWN + n0;

#pragma unroll
    for (int i = 0; i < 2; i++) {
        int j = t + i * 512;
        int row = j >> 3, seg = j & 7;
        cp16(sb + G1_WS0 + (uint32_t)(row * 72 + seg * 8) * 2,
             W + (size_t)row * CIN + seg * 8);
    }
#pragma unroll
    for (int i = 0; i < 2; i++) {
        int j = t + i * 512;
        int k = j >> 4, seg = j & 15;
        cp16(sb + G1_XS0 + (uint32_t)(k * 136 + seg * 8) * 2,
             Xin + (size_t)k * HWN + seg * 8);
    }
    CP_COMMIT();
    CP_WAIT0();
    __syncthreads();

    float acc[2][4][4];
#pragma unroll
    for (int i = 0; i < 2; i++)
#pragma unroll
        for (int j = 0; j < 4; j++)
#pragma unroll
            for (int k = 0; k < 4; k++) acc[i][j][k] = 0.0f;

    for (int c = 0; c < 4; c++) {
        int s = c & 1;
        uint32_t wbase = sb + (s ? G1_WS1 : G1_WS0);
        uint32_t xbase = sb + (s ? G1_XS1 : G1_XS0);
        if (c < 3) {
            int k0n = (c + 1) * 64;
            uint32_t wdst = sb + (s ? G1_WS0 : G1_WS1);
            uint32_t xdst = sb + (s ? G1_XS0 : G1_XS1);
#pragma unroll
            for (int i = 0; i < 2; i++) {
                int j = t + i * 512;
                int row = j >> 3, seg = j & 7;
                cp16(wdst + (uint32_t)(row * 72 + seg * 8) * 2,
                     W + (size_t)row * CIN + k0n + seg * 8);
            }
#pragma unroll
            for (int i = 0; i < 2; i++) {
                int j = t + i * 512;
                int k = j >> 4, seg = j & 15;
                cp16(xdst + (uint32_t)(k * 136 + seg * 8) * 2,
                     Xin + (size_t)(k0n + k) * HWN + seg * 8);
            }
            CP_COMMIT();
        }
#pragma unroll
        for (int ks = 0; ks < 4; ks++) {
            int kk = ks * 16;
            uint32_t ah[2][4];
#pragma unroll
            for (int mf = 0; mf < 2; mf++) {
                int row = wm * 32 + mf * 16 + (lane & 15);
                int col = kk + (lane >> 4) * 8;
                ldsm4(ah[mf], wbase + (uint32_t)(row * 72 + col) * 2);
            }
#pragma unroll
            for (int r = 0; r < 2; r++) {
                int kr = kk + (lane & 15);
                int coln = wn * 32 + r * 16 + (lane >> 4) * 8;
                uint32_t bh[4];
                ldsm4t(bh, xbase + (uint32_t)(kr * 136 + coln) * 2);
#pragma unroll
                for (int mf = 0; mf < 2; mf++) {
                    mma_f16(acc[mf][r * 2],     ah[mf], bh[0], bh[1]);
                    mma_f16(acc[mf][r * 2 + 1], ah[mf], bh[2], bh[3]);
                }
            }
        }
        if (c < 3) {
            CP_WAIT0();
            __syncthreads();
        }
    }

    int r0 = m0 + wm * 32 + (lane >> 2);
    float bv[4] = { g_bp[r0], g_bp[r0 + 8], g_bp[r0 + 16], g_bp[r0 + 24] };
#pragma unroll
    for (int mf = 0; mf < 2; mf++)
#pragma unroll
        for (int nf = 0; nf < 4; nf++) {
            int row = m0 + wm * 32 + mf * 16 + (lane >> 2);
            int col = n0 + wn * 32 + nf * 8 + (lane & 3) * 2;
            float bb0 = bv[mf * 2], bb1 = bv[mf * 2 + 1];
            *reinterpret_cast<float2*>(&out[((size_t)(b * MQ) + row) * HWN + col]) =
                make_float2(acc[mf][nf][0] + bb0, acc[mf][nf][1] + bb0);
            *reinterpret_cast<float2*>(&out[((size_t)(b * MQ) + row + 8) * HWN + col]) =
                make_float2(acc[mf][nf][2] + bb1, acc[mf][nf][3] + bb1);
        }
}

// ---------------- launch ------------------------------------------------------------
extern "C" void kernel_launch(void* const* d_in, const int* in_sizes, int n_in,
                              void* d_out, int out_size)
{
    const float* input = (const float*)d_in[0];
    const float* Wq  = (const float*)d_in[2];
    const float* gq  = (const float*)d_in[3];
    const float* bq  = (const float*)d_in[4];
    const float* mq  = (const float*)d_in[5];
    const float* vq  = (const float*)d_in[6];
    const float* Wkv = (const float*)d_in[7];
    const float* gkv = (const float*)d_in[8];
    const float* bkv = (const float*)d_in[9];
    const float* mkv = (const float*)d_in[10];
    const float* vkv = (const float*)d_in[11];
    const float* Wp  = (const float*)d_in[12];
    const float* gp  = (const float*)d_in[13];
    const float* bp  = (const float*)d_in[14];
    const float* mp  = (const float*)d_in[15];
    const float* vp  = (const float*)d_in[16];
    float* out = (float*)d_out;

    cudaFuncSetAttribute(qattn_kernel, cudaFuncAttributeMaxDynamicSharedMemorySize, QA_SMEM);
    cudaFuncSetAttribute(proj_kernel, cudaFuncAttributeMaxDynamicSharedMemorySize, G1_SMEM);

    fold_kernel<<<512, 256>>>(Wq, gq, bq, mq, vq,
                              Wkv, gkv, bkv, mkv, vkv,
                              Wp, gp, bp, mp, vp);
    kvctx_kernel<<<dim3(HWN / 256, BATCH), 256>>>(input);
    qattn_kernel<<<dim3(HWN / 128, 2, BATCH), 512, QA_SMEM>>>();
    proj_kernel<<<dim3(HWN / 128, 2, BATCH), 512, G1_SMEM>>>(out);
}

// round 17
// speedup vs baseline: 1.1346x; 1.0060x over previous
#include <cuda_runtime.h>
#include <cuda_fp16.h>
#include <cstdint>

#define BATCH 16
#define CIN   256
#define HWN   4096
#define DHEAD 32
#define NHEAD 8
#define MQ    256

// ---------------- scratch (device globals) -----------------------------------
__device__ float g_ctxT[BATCH * DHEAD * DHEAD];   // UNNORMALIZED ctxT'
__device__ float g_rs[BATCH * DHEAD];             // row exp-sums S_e
__device__ float g_Wkv[DHEAD * CIN]; __device__ float g_bkv[DHEAD];
__device__ float g_bq [MQ];          __device__ float g_bp [CIN];
__device__ __half g_WH[2][MQ * CIN];
__device__ __half g_XIN[(size_t)BATCH * CIN * HWN];
__device__ __half g_XF[(size_t)BATCH * MQ * HWN];

// ---------------- f32x2 helpers ------------------------------------------------
#define PACKF2(u, lo, hi) asm("mov.b64 %0, {%1, %2};" : "=l"(u) : "f"(lo), "f"(hi))
#define UNPACKF2(lo, hi, u) asm("mov.b64 {%0, %1}, %2;" : "=f"(lo), "=f"(hi) : "l"(u))
#define FMAF2(c, a, b) asm("fma.rn.f32x2 %0, %1, %2, %0;" : "+l"(c) : "l"(a), "l"(b))

// ---------------- mma / async helpers -------------------------------------------
__device__ __forceinline__ void ldsm4(uint32_t* r, uint32_t addr) {
    asm volatile("ldmatrix.sync.aligned.m8n8.x4.shared.b16 {%0,%1,%2,%3}, [%4];\n"
        : "=r"(r[0]), "=r"(r[1]), "=r"(r[2]), "=r"(r[3]) : "r"(addr));
}
__device__ __forceinline__ void ldsm4t(uint32_t* r, uint32_t addr) {
    asm volatile("ldmatrix.sync.aligned.m8n8.x4.trans.shared.b16 {%0,%1,%2,%3}, [%4];\n"
        : "=r"(r[0]), "=r"(r[1]), "=r"(r[2]), "=r"(r[3]) : "r"(addr));
}
__device__ __forceinline__ void mma_f16(float* c, const uint32_t* a,
                                        uint32_t b0, uint32_t b1) {
    asm volatile(
        "mma.sync.aligned.m16n8k16.row.col.f32.f16.f16.f32 "
        "{%0,%1,%2,%3}, {%4,%5,%6,%7}, {%8,%9}, {%0,%1,%2,%3};\n"
        : "+f"(c[0]), "+f"(c[1]), "+f"(c[2]), "+f"(c[3])
        : "r"(a[0]), "r"(a[1]), "r"(a[2]), "r"(a[3]), "r"(b0), "r"(b1));
}
__device__ __forceinline__ uint32_t packh2(__half a, __half b) {
    return (uint32_t)__half_as_ushort(a) | ((uint32_t)__half_as_ushort(b) << 16);
}
__device__ __forceinline__ void cp16(uint32_t saddr, const void* gptr) {
    asm volatile("cp.async.cg.shared.global [%0], [%1], 16;" :: "r"(saddr), "l"(gptr));
}
#define CP_COMMIT() asm volatile("cp.async.commit_group;" ::: "memory")
#define CP_WAIT0()  asm volatile("cp.async.wait_group 0;" ::: "memory")

// ---------------- 1) fold BN + fp16 weight plane + zero accumulators -----------
__global__ void fold_kernel(
    const float* __restrict__ Wq, const float* __restrict__ gq, const float* __restrict__ bq,
    const float* __restrict__ mq, const float* __restrict__ vq,
    const float* __restrict__ Wkv, const float* __restrict__ gkv, const float* __restrict__ bkv,
    const float* __restrict__ mkv, const float* __restrict__ vkv,
    const float* __restrict__ Wp, const float* __restrict__ gp, const float* __restrict__ bp,
    const float* __restrict__ mp, const float* __restrict__ vp)
{
    int t = blockIdx.x * blockDim.x + threadIdx.x;
    int stride = gridDim.x * blockDim.x;
    const float eps = 1e-5f;
    for (int i = t; i < BATCH * DHEAD * DHEAD; i += stride) g_ctxT[i] = 0.0f;
    for (int i = t; i < BATCH * DHEAD; i += stride) g_rs[i] = 0.0f;
    for (int i = t; i < MQ; i += stride) {
        float s = gq[i] * rsqrtf(vq[i] + eps); g_bq[i] = bq[i] - mq[i] * s;
    }
    for (int i = t; i < CIN; i += stride) {
        float s = gp[i] * rsqrtf(vp[i] + eps); g_bp[i] = bp[i] - mp[i] * s;
    }
    for (int i = t; i < DHEAD; i += stride) {
        float s = gkv[i] * rsqrtf(vkv[i] + eps); g_bkv[i] = bkv[i] - mkv[i] * s;
    }
    for (int i = t; i < DHEAD * CIN; i += stride) {
        int o = i / CIN; g_Wkv[i] = Wkv[i] * gkv[o] * rsqrtf(vkv[o] + eps);
    }
    for (int i = t; i < MQ * CIN; i += stride) {
        int m = i >> 8;
        g_WH[0][i] = __float2half_rn(Wq[i] * gq[m] * rsqrtf(vq[m] + eps));
        g_WH[1][i] = __float2half_rn(Wp[i] * gp[m] * rsqrtf(vp[m] + eps));
    }
}

// ---------------- 2) FUSED kv + ctx with transposed tail layout -----------------
// [pos][36] layout: ps reads become one broadcast LDS.128; kv read stays
// conflict-free (d = lane -> consecutive floats). Staging uses float4 STS.
__global__ __launch_bounds__(256) void kvctx_kernel(const float* __restrict__ X)
{
    __shared__ __align__(16) float Ws[CIN][DHEAD];     // 32 KB
    __shared__ float bs[DHEAD];
    __shared__ __align__(16) float kv2[128][36];       // 18 KB  [pos][d]
    __shared__ __align__(16) float ps2[128][36];       // 18 KB  [pos][e]

    int t = threadIdx.x;
    for (int i = t; i < DHEAD * CIN; i += 256) {
        int m = i / CIN, k = i % CIN;
        Ws[k][m] = g_Wkv[i];
    }
    if (t < DHEAD) bs[t] = g_bkv[t];
    __syncthreads();

    int b = blockIdx.y;
    int n = blockIdx.x * 256 + t;
    const float* x = X + (size_t)b * CIN * HWN + n;
    __half* xin = g_XIN + (size_t)b * CIN * HWN + n;

    unsigned long long acc[16];
#pragma unroll
    for (int j = 0; j < 16; j++) PACKF2(acc[j], bs[2 * j], bs[2 * j + 1]);

#pragma unroll 4
    for (int k = 0; k < CIN; k++) {
        float xv = x[(size_t)k * HWN];
        xin[(size_t)k * HWN] = __float2half_rn(xv);
        unsigned long long xp; PACKF2(xp, xv, xv);
        const ulonglong2* wr = reinterpret_cast<const ulonglong2*>(&Ws[k][0]);
#pragma unroll
        for (int j = 0; j < 8; j++) {
            ulonglong2 w = wr[j];
            FMAF2(acc[2 * j],     w.x, xp);
            FMAF2(acc[2 * j + 1], w.y, xp);
        }
    }

    float kvf[32];
#pragma unroll
    for (int j = 0; j < 16; j++) UNPACKF2(kvf[2 * j], kvf[2 * j + 1], acc[j]);
    float pexp[32];
#pragma unroll
    for (int j = 0; j < 32; j++) pexp[j] = __expf(kvf[j]);

    int d = t & 31, e0 = (t >> 5) * 4;
    int half_id = t >> 7, pos = t & 127;
    float cacc[4] = {0.f, 0.f, 0.f, 0.f};
    float srow = 0.0f;
    int r = t >> 3, seg = t & 7;

    for (int h = 0; h < 2; h++) {
        __syncthreads();
        if (half_id == h) {
#pragma unroll
            for (int j = 0; j < 8; j++) {
                *reinterpret_cast<float4*>(&kv2[pos][j * 4]) =
                    make_float4(kvf[j*4], kvf[j*4+1], kvf[j*4+2], kvf[j*4+3]);
                *reinterpret_cast<float4*>(&ps2[pos][j * 4]) =
                    make_float4(pexp[j*4], pexp[j*4+1], pexp[j*4+2], pexp[j*4+3]);
            }
        }
        __syncthreads();
        // row-sum partials: thread sums 16 positions of column r
#pragma unroll 4
        for (int q = 0; q < 16; q++) srow += ps2[seg * 16 + q][r];
        // ctxT' partials: 1 broadcast LDS.128 + 1 LDS.32 + 4 FFMA per position
#pragma unroll 4
        for (int nn = 0; nn < 128; nn++) {
            float4 pe = *reinterpret_cast<const float4*>(&ps2[nn][e0]);
            float kd = kv2[nn][d];
            cacc[0] += pe.x * kd;
            cacc[1] += pe.y * kd;
            cacc[2] += pe.z * kd;
            cacc[3] += pe.w * kd;
        }
    }

#pragma unroll
    for (int o = 4; o > 0; o >>= 1) srow += __shfl_xor_sync(~0u, srow, o);
    if (seg == 0) atomicAdd(&g_rs[b * DHEAD + r], srow);
#pragma unroll
    for (int j = 0; j < 4; j++)
        atomicAdd(&g_ctxT[b * 1024 + d * 32 + (e0 + j)], cacc[j]);
}

// ---------------- 3) qattn: 512 thr / 16 warps / warp tile 32x32 (R11 config) -----
#define QA_WS0  0
#define QA_WS1  18432
#define QA_XS0  36864
#define QA_XS1  54272
#define QA_CSH  71680
#define QA_CSL  74240
#define QA_BIAS 76800
#define QA_SMEM 77312
#define QA_Q    0

__global__ void __launch_bounds__(512, 2) qattn_kernel()
{
    extern __shared__ __align__(16) char smem[];
    __half* sCh = reinterpret_cast<__half*>(smem + QA_CSH);
    __half* sCl = reinterpret_cast<__half*>(smem + QA_CSL);
    float* sBias = reinterpret_cast<float*>(smem + QA_BIAS);
    __half* sQ  = reinterpret_cast<__half*>(smem + QA_Q);
    uint32_t sb = (uint32_t)__cvta_generic_to_shared(smem);

    int t = threadIdx.x, lane = t & 31, wid = t >> 5;
    int wm = wid >> 2, wn = wid & 3;
    int nt = blockIdx.x, mt = blockIdx.y, b = blockIdx.z;
    int n0 = nt * 128, m0 = mt * 128;
    const __half* W = g_WH[0] + (size_t)m0 * CIN;
    const __half* Xin = g_XIN + (size_t)b * CIN * HWN + n0;

    for (int i = t; i < 1024; i += 512) {
        int d = i >> 5, e = i & 31;
        float f = g_ctxT[b * 1024 + i] / g_rs[b * DHEAD + e];
        __half h = __float2half_rn(f);
        sCh[d * 40 + e] = h;
        sCl[d * 40 + e] = __float2half_rn(f - __half2float(h));
    }
    if (t < 128) sBias[t] = g_bq[m0 + t];

#pragma unroll
    for (int i = 0; i < 2; i++) {
        int j = t + i * 512;
        int row = j >> 3, seg = j & 7;
        cp16(sb + QA_WS0 + (uint32_t)(row * 72 + seg * 8) * 2,
             W + (size_t)row * CIN + seg * 8);
    }
#pragma unroll
    for (int i = 0; i < 2; i++) {
        int j = t + i * 512;
        int k = j >> 4, seg = j & 15;
        cp16(sb + QA_XS0 + (uint32_t)(k * 136 + seg * 8) * 2,
             Xin + (size_t)k * HWN + seg * 8);
    }
    CP_COMMIT();
    CP_WAIT0();
    __syncthreads();

    float acc[2][4][4];
#pragma unroll
    for (int i = 0; i < 2; i++)
#pragma unroll
        for (int j = 0; j < 4; j++)
#pragma unroll
            for (int k = 0; k < 4; k++) acc[i][j][k] = 0.0f;

    for (int c = 0; c < 4; c++) {
        int s = c & 1;
        uint32_t wbase = sb + (s ? QA_WS1 : QA_WS0);
        uint32_t xbase = sb + (s ? QA_XS1 : QA_XS0);
        if (c < 3) {
            int k0n = (c + 1) * 64;
            uint32_t wdst = sb + (s ? QA_WS0 : QA_WS1);
            uint32_t xdst = sb + (s ? QA_XS0 : QA_XS1);
#pragma unroll
            for (int i = 0; i < 2; i++) {
                int j = t + i * 512;
                int row = j >> 3, seg = j & 7;
                cp16(wdst + (uint32_t)(row * 72 + seg * 8) * 2,
                     W + (size_t)row * CIN + k0n + seg * 8);
            }
#pragma unroll
            for (int i = 0; i < 2; i++) {
                int j = t + i * 512;
                int k = j >> 4, seg = j & 15;
                cp16(xdst + (uint32_t)(k * 136 + seg * 8) * 2,
                     Xin + (size_t)(k0n + k) * HWN + seg * 8);
            }
            CP_COMMIT();
        }
#pragma unroll
        for (int ks = 0; ks < 4; ks++) {
            int kk = ks * 16;
            uint32_t ah[2][4];
#pragma unroll
            for (int mf = 0; mf < 2; mf++) {
                int row = wm * 32 + mf * 16 + (lane & 15);
                int col = kk + (lane >> 4) * 8;
                ldsm4(ah[mf], wbase + (uint32_t)(row * 72 + col) * 2);
            }
#pragma unroll
            for (int r = 0; r < 2; r++) {
                int kr = kk + (lane & 15);
                int coln = wn * 32 + r * 16 + (lane >> 4) * 8;
                uint32_t bh[4];
                ldsm4t(bh, xbase + (uint32_t)(kr * 136 + coln) * 2);
#pragma unroll
                for (int mf = 0; mf < 2; mf++) {
                    mma_f16(acc[mf][r * 2],     ah[mf], bh[0], bh[1]);
                    mma_f16(acc[mf][r * 2 + 1], ah[mf], bh[2], bh[3]);
                }
            }
        }
        if (c < 3) {
            CP_WAIT0();
            __syncthreads();
        }
    }
    __syncthreads();

    {
        int r0 = wm * 32 + (lane >> 2);
        float bv[4] = { sBias[r0], sBias[r0 + 8], sBias[r0 + 16], sBias[r0 + 24] };
#pragma unroll
        for (int mf = 0; mf < 2; mf++)
#pragma unroll
            for (int nf = 0; nf < 4; nf++)
#pragma unroll
                for (int k = 0; k < 4; k++)
                    acc[mf][nf][k] += bv[mf * 2 + (k >> 1)];
    }
#pragma unroll
    for (int nf = 0; nf < 4; nf++) {
#pragma unroll
        for (int p = 0; p < 2; p++) {
            float m = fmaxf(fmaxf(acc[0][nf][p], acc[0][nf][p + 2]),
                            fmaxf(acc[1][nf][p], acc[1][nf][p + 2]));
            m = fmaxf(m, __shfl_xor_sync(~0u, m, 4));
            m = fmaxf(m, __shfl_xor_sync(~0u, m, 8));
            m = fmaxf(m, __shfl_xor_sync(~0u, m, 16));
            float e00 = __expf(acc[0][nf][p] - m);
            float e01 = __expf(acc[0][nf][p + 2] - m);
            float e10 = __expf(acc[1][nf][p] - m);
            float e11 = __expf(acc[1][nf][p + 2] - m);
            float s = e00 + e01 + e10 + e11;
            s += __shfl_xor_sync(~0u, s, 4);
            s += __shfl_xor_sync(~0u, s, 8);
            s += __shfl_xor_sync(~0u, s, 16);
            float inv = 1.0f / s;
            acc[0][nf][p]     = e00 * inv;
            acc[0][nf][p + 2] = e01 * inv;
            acc[1][nf][p]     = e10 * inv;
            acc[1][nf][p + 2] = e11 * inv;
        }
    }
#pragma unroll
    for (int mf = 0; mf < 2; mf++)
#pragma unroll
        for (int nf = 0; nf < 4; nf++) {
            int row = wm * 32 + mf * 16 + (lane >> 2);
            int col = wn * 32 + nf * 8 + (lane & 3) * 2;
            *reinterpret_cast<uint32_t*>(sQ + row * 136 + col) =
                packh2(__float2half_rn(acc[mf][nf][0]), __float2half_rn(acc[mf][nf][1]));
            *reinterpret_cast<uint32_t*>(sQ + (row + 8) * 136 + col) =
                packh2(__float2half_rn(acc[mf][nf][2]), __float2half_rn(acc[mf][nf][3]));
        }
    __syncwarp();

    float att[2][4][4];
#pragma unroll
    for (int i = 0; i < 2; i++)
#pragma unroll
        for (int j = 0; j < 4; j++)
#pragma unroll
            for (int k = 0; k < 4; k++) att[i][j][k] = 0.0f;

#pragma unroll
    for (int kf = 0; kf < 2; kf++) {
        uint32_t ach[2][4], acl[2][4];
#pragma unroll
        for (int mf = 0; mf < 2; mf++) {
            int row = mf * 16 + (lane & 15);
            int col = kf * 16 + (lane >> 4) * 8;
            uint32_t a_addr = sb + QA_CSH + (uint32_t)(row * 40 + col) * 2;
            ldsm4(ach[mf], a_addr);
            ldsm4(acl[mf], a_addr + (QA_CSL - QA_CSH));
        }
#pragma unroll
        for (int r = 0; r < 2; r++) {
            int kr = wm * 32 + kf * 16 + (lane & 15);
            int coln = wn * 32 + r * 16 + (lane >> 4) * 8;
            uint32_t qb[4];
            ldsm4t(qb, sb + QA_Q + (uint32_t)(kr * 136 + coln) * 2);
#pragma unroll
            for (int mf = 0; mf < 2; mf++) {
                mma_f16(att[mf][r * 2],     ach[mf], qb[0], qb[1]);
                mma_f16(att[mf][r * 2 + 1], ach[mf], qb[2], qb[3]);
                mma_f16(att[mf][r * 2],     acl[mf], qb[0], qb[1]);
                mma_f16(att[mf][r * 2 + 1], acl[mf], qb[2], qb[3]);
            }
        }
    }

#pragma unroll
    for (int mf = 0; mf < 2; mf++)
#pragma unroll
        for (int nf = 0; nf < 4; nf++) {
            int row = m0 + wm * 32 + mf * 16 + (lane >> 2);
            int col = n0 + wn * 32 + nf * 8 + (lane & 3) * 2;
            float v0 = fmaxf(att[mf][nf][0], 0.f), v1 = fmaxf(att[mf][nf][1], 0.f);
            float v2 = fmaxf(att[mf][nf][2], 0.f), v3 = fmaxf(att[mf][nf][3], 0.f);
            *reinterpret_cast<uint32_t*>(&g_XF[((size_t)(b * MQ) + row) * HWN + col]) =
                packh2(__float2half_rn(v0), __float2half_rn(v1));
            *reinterpret_cast<uint32_t*>(&g_XF[((size_t)(b * MQ) + row + 8) * HWN + col]) =
                packh2(__float2half_rn(v2), __float2half_rn(v3));
        }
}

// ---------------- 4) proj: 512 thr / 16 warps / warp tile 32x32 (R11 config) ------
#define G1_WS0  0
#define G1_WS1  18432
#define G1_XS0  36864
#define G1_XS1  54272
#define G1_SMEM 71680

__global__ void __launch_bounds__(512, 2) proj_kernel(float* __restrict__ out)
{
    extern __shared__ __align__(16) char smem[];
    uint32_t sb = (uint32_t)__cvta_generic_to_shared(smem);

    int t = threadIdx.x, lane = t & 31, wid = t >> 5;
    int wm = wid >> 2, wn = wid & 3;
    int nt = blockIdx.x, mt = blockIdx.y, b = blockIdx.z;
    int n0 = nt * 128, m0 = mt * 128;
    const __half* W = g_WH[1] + (size_t)m0 * CIN;
    const __half* Xin = g_XF + (size_t)b * MQ * HWN + n0;

#pragma unroll
    for (int i = 0; i < 2; i++) {
        int j = t + i * 512;
        int row = j >> 3, seg = j & 7;
        cp16(sb + G1_WS0 + (uint32_t)(row * 72 + seg * 8) * 2,
             W + (size_t)row * CIN + seg * 8);
    }
#pragma unroll
    for (int i = 0; i < 2; i++) {
        int j = t + i * 512;
        int k = j >> 4, seg = j & 15;
        cp16(sb + G1_XS0 + (uint32_t)(k * 136 + seg * 8) * 2,
             Xin + (size_t)k * HWN + seg * 8);
    }
    CP_COMMIT();
    CP_WAIT0();
    __syncthreads();

    float acc[2][4][4];
#pragma unroll
    for (int i = 0; i < 2; i++)
#pragma unroll
        for (int j = 0; j < 4; j++)
#pragma unroll
            for (int k = 0; k < 4; k++) acc[i][j][k] = 0.0f;

    for (int c = 0; c < 4; c++) {
        int s = c & 1;
        uint32_t wbase = sb + (s ? G1_WS1 : G1_WS0);
        uint32_t xbase = sb + (s ? G1_XS1 : G1_XS0);
        if (c < 3) {
            int k0n = (c + 1) * 64;
            uint32_t wdst = sb + (s ? G1_WS0 : G1_WS1);
            uint32_t xdst = sb + (s ? G1_XS0 : G1_XS1);
#pragma unroll
            for (int i = 0; i < 2; i++) {
                int j = t + i * 512;
                int row = j >> 3, seg = j & 7;
                cp16(wdst + (uint32_t)(row * 72 + seg * 8) * 2,
                     W + (size_t)row * CIN + k0n + seg * 8);
            }
#pragma unroll
            for (int i = 0; i < 2; i++) {
                int j = t + i * 512;
                int k = j >> 4, seg = j & 15;
                cp16(xdst + (uint32_t)(k * 136 + seg * 8) * 2,
                     Xin + (size_t)(k0n + k) * HWN + seg * 8);
            }
            CP_COMMIT();
        }
#pragma unroll
        for (int ks = 0; ks < 4; ks++) {
            int kk = ks * 16;
            uint32_t ah[2][4];
#pragma unroll
            for (int mf = 0; mf < 2; mf++) {
                int row = wm * 32 + mf * 16 + (lane & 15);
                int col = kk + (lane >> 4) * 8;
                ldsm4(ah[mf], wbase + (uint32_t)(row * 72 + col) * 2);
            }
#pragma unroll
            for (int r = 0; r < 2; r++) {
                int kr = kk + (lane & 15);
                int coln = wn * 32 + r * 16 + (lane >> 4) * 8;
                uint32_t bh[4];
                ldsm4t(bh, xbase + (uint32_t)(kr * 136 + coln) * 2);
#pragma unroll
                for (int mf = 0; mf < 2; mf++) {
                    mma_f16(acc[mf][r * 2],     ah[mf], bh[0], bh[1]);
                    mma_f16(acc[mf][r * 2 + 1], ah[mf], bh[2], bh[3]);
                }
            }
        }
        if (c < 3) {
            CP_WAIT0();
            __syncthreads();
        }
    }

    int r0 = m0 + wm * 32 + (lane >> 2);
    float bv[4] = { g_bp[r0], g_bp[r0 + 8], g_bp[r0 + 16], g_bp[r0 + 24] };
#pragma unroll
    for (int mf = 0; mf < 2; mf++)
#pragma unroll
        for (int nf = 0; nf < 4; nf++) {
            int row = m0 + wm * 32 + mf * 16 + (lane >> 2);
            int col = n0 + wn * 32 + nf * 8 + (lane & 3) * 2;
            float bb0 = bv[mf * 2], bb1 = bv[mf * 2 + 1];
            *reinterpret_cast<float2*>(&out[((size_t)(b * MQ) + row) * HWN + col]) =
                make_float2(acc[mf][nf][0] + bb0, acc[mf][nf][1] + bb0);
            *reinterpret_cast<float2*>(&out[((size_t)(b * MQ) + row + 8) * HWN + col]) =
                make_float2(acc[mf][nf][2] + bb1, acc[mf][nf][3] + bb1);
        }
}

// ---------------- launch ------------------------------------------------------------
extern "C" void kernel_launch(void* const* d_in, const int* in_sizes, int n_in,
                              void* d_out, int out_size)
{
    const float* input = (const float*)d_in[0];
    const float* Wq  = (const float*)d_in[2];
    const float* gq  = (const float*)d_in[3];
    const float* bq  = (const float*)d_in[4];
    const float* mq  = (const float*)d_in[5];
    const float* vq  = (const float*)d_in[6];
    const float* Wkv = (const float*)d_in[7];
    const float* gkv = (const float*)d_in[8];
    const float* bkv = (const float*)d_in[9];
    const float* mkv = (const float*)d_in[10];
    const float* vkv = (const float*)d_in[11];
    const float* Wp  = (const float*)d_in[12];
    const float* gp  = (const float*)d_in[13];
    const float* bp  = (const float*)d_in[14];
    const float* mp  = (const float*)d_in[15];
    const float* vp  = (const float*)d_in[16];
    float* out = (float*)d_out;

    cudaFuncSetAttribute(qattn_kernel, cudaFuncAttributeMaxDynamicSharedMemorySize, QA_SMEM);
    cudaFuncSetAttribute(proj_kernel, cudaFuncAttributeMaxDynamicSharedMemorySize, G1_SMEM);

    fold_kernel<<<512, 256>>>(Wq, gq, bq, mq, vq,
                              Wkv, gkv, bkv, mkv, vkv,
                              Wp, gp, bp, mp, vp);
    kvctx_kernel<<<dim3(HWN / 256, BATCH), 256>>>(input);
    qattn_kernel<<<dim3(HWN / 128, 2, BATCH), 512, QA_SMEM>>>();
    proj_kernel<<<dim3(HWN / 128, 2, BATCH), 512, G1_SMEM>>>(out);
}